// round 15
// baseline (speedup 1.0000x reference)
#include <cuda_runtime.h>
#include <math.h>

#define TKN 8192
#define DIM 1024
#define HID 2048
#define NE  16
#define RBLK 256            // router blocks (TKN/32)
#define YB  64              // slots token-blocks (TKN/128)

// ---------------- scratch (no allocation allowed) ----------------
__device__ float g_exps[TKN * NE];      // exp(logits) (dispatch numerator)
__device__ float g_comb[TKN * NE];      // combine = row softmax
__device__ float g_cpart[NE * RBLK];    // per-block colsum partials [e][block]
__device__ float g_upart[NE * RBLK];    // per-block usage partials  [e][block]
__device__ float g_epart[RBLK];         // per-block entropy partials
__device__ float g_spart[YB * NE * DIM];// per-y-block slot partials [y][e][d]
__device__ float g_slots[NE * DIM];     // dispatch^T @ x
__device__ float g_hbuf[NE * HID];      // fc1 out -> LN+GELU in place
__device__ float g_sout[NE * DIM];      // fc2 out

// ---------------- kernel 1: logits + both softmaxes + partial stats -------
// 256 blocks x 256 threads. Block tile: 32 tokens x 16 experts.
// Warps 0-3: experts 0-7 for token groups 0-3; warps 4-7: experts 8-15.
__global__ void __launch_bounds__(256) k_router(const float* __restrict__ x,
                                                const float* __restrict__ rw) {
    extern __shared__ float4 rwsh[];          // 16 * 256 float4 = 64 KB
    __shared__ float lsh[32 * NE];            // logit tile
    const int tid = threadIdx.x;

    const float4* rw4 = reinterpret_cast<const float4*>(rw);
#pragma unroll
    for (int i = 0; i < 16; i++) rwsh[tid + i * 256] = rw4[tid + i * 256];
    __syncthreads();

    const int warp = tid >> 5, lane = tid & 31;
    const int wg = warp & 3;                  // token subgroup (8 tokens)
    const int eb = (warp >> 2) * 8;           // expert base: 0 or 8
    const int t0 = blockIdx.x * 32 + wg * 8;

    float acc[8][8];
#pragma unroll
    for (int e = 0; e < 8; e++)
#pragma unroll
        for (int j = 0; j < 8; j++) acc[e][j] = 0.f;

    const float4* x4 = reinterpret_cast<const float4*>(x);
#pragma unroll
    for (int k = 0; k < 8; k++) {
        float4 xv[8];
#pragma unroll
        for (int j = 0; j < 8; j++)
            xv[j] = x4[(size_t)(t0 + j) * 256 + k * 32 + lane];
#pragma unroll
        for (int e = 0; e < 8; e++) {
            float4 r = rwsh[(eb + e) * 256 + k * 32 + lane];
#pragma unroll
            for (int j = 0; j < 8; j++) {
                acc[e][j] = fmaf(xv[j].x, r.x, acc[e][j]);
                acc[e][j] = fmaf(xv[j].y, r.y, acc[e][j]);
                acc[e][j] = fmaf(xv[j].z, r.z, acc[e][j]);
                acc[e][j] = fmaf(xv[j].w, r.w, acc[e][j]);
            }
        }
    }
#pragma unroll
    for (int e = 0; e < 8; e++)
#pragma unroll
        for (int j = 0; j < 8; j++)
#pragma unroll
            for (int m = 16; m > 0; m >>= 1)
                acc[e][j] += __shfl_xor_sync(0xffffffffu, acc[e][j], m);

    // every lane has all 64 sums; one writer per (e,j)
#pragma unroll
    for (int e = 0; e < 8; e++)
#pragma unroll
        for (int j = 0; j < 8; j++)
            if (lane == ((j * 8 + e) & 31))
                lsh[(wg * 8 + j) * NE + eb + e] = acc[e][j];
    __syncthreads();

    // warp 0: row softmax over 16 experts, one token per lane (32 tokens)
    if (tid < 32) {
        const int t = blockIdx.x * 32 + tid;
        float l[16], raw[16], comb[16];
        float mx = -1e30f;
#pragma unroll
        for (int e = 0; e < NE; e++) { l[e] = lsh[tid * NE + e]; mx = fmaxf(mx, l[e]); }
        float den = 0.f;
#pragma unroll
        for (int e = 0; e < NE; e++) { comb[e] = expf(l[e] - mx); den += comb[e]; }
        const float rden = 1.0f / den;
        float ent = 0.f;
#pragma unroll
        for (int e = 0; e < NE; e++) {
            comb[e] *= rden;
            raw[e]   = expf(l[e]);
            ent     -= comb[e] * logf(comb[e] + 1e-8f);
        }
#pragma unroll
        for (int e = 0; e < NE; e++) {
            g_exps[t * NE + e] = raw[e];
            g_comb[t * NE + e] = comb[e];
        }
        // per-block partial sums across the 32 tokens (full-warp butterfly)
#pragma unroll
        for (int e = 0; e < NE; e++) {
            float cs = raw[e], us = comb[e];
#pragma unroll
            for (int m = 16; m > 0; m >>= 1) {
                cs += __shfl_xor_sync(0xffffffffu, cs, m);
                us += __shfl_xor_sync(0xffffffffu, us, m);
            }
            if (tid == e) {
                g_cpart[e * RBLK + blockIdx.x] = cs;
                g_upart[e * RBLK + blockIdx.x] = us;
            }
        }
#pragma unroll
        for (int m = 16; m > 0; m >>= 1)
            ent += __shfl_xor_sync(0xffffffffu, ent, m);
        if (tid == 0) g_epart[blockIdx.x] = ent;
    }
}

// ---------------- kernel 2: slot partials = dispatch^T @ x (per y-block) ---
// grid (DIM/256, YB). Block: 256 d-columns x 128 tokens. Writes partials —
// no atomics, no ordering assumptions.
__global__ void __launch_bounds__(256) k_slots(const float* __restrict__ x) {
    __shared__ float4 wts[128 * 4];
    __shared__ float  inv[NE];
    const int tid = threadIdx.x;
    {   // reduce colsum partials: 16 threads per expert
        const int e = tid >> 4, sub = tid & 15;
        float s = 0.f;
#pragma unroll
        for (int i = 0; i < 16; i++) s += g_cpart[e * RBLK + sub + i * 16];
#pragma unroll
        for (int m = 8; m > 0; m >>= 1) s += __shfl_xor_sync(0xffffffffu, s, m);
        if (sub == 0) inv[e] = 1.0f / s;
    }
    __syncthreads();

    const int tbase = blockIdx.y * 128;
    if (tid < 128) {
        const float4* ge = reinterpret_cast<const float4*>(g_exps) + (size_t)(tbase + tid) * 4;
        float4 a = ge[0], b = ge[1], c = ge[2], d4 = ge[3];
        a.x *= inv[0];  a.y *= inv[1];  a.z *= inv[2];  a.w *= inv[3];
        b.x *= inv[4];  b.y *= inv[5];  b.z *= inv[6];  b.w *= inv[7];
        c.x *= inv[8];  c.y *= inv[9];  c.z *= inv[10]; c.w *= inv[11];
        d4.x *= inv[12]; d4.y *= inv[13]; d4.z *= inv[14]; d4.w *= inv[15];
        wts[tid * 4 + 0] = a; wts[tid * 4 + 1] = b;
        wts[tid * 4 + 2] = c; wts[tid * 4 + 3] = d4;
    }
    __syncthreads();

    const int d = blockIdx.x * 256 + tid;
    const float* xp = x + (size_t)tbase * DIM + d;
    float acc[NE];
#pragma unroll
    for (int e = 0; e < NE; e++) acc[e] = 0.f;

    for (int tt = 0; tt < 128; tt += 8) {
        float xv[8];
#pragma unroll
        for (int u = 0; u < 8; u++) xv[u] = xp[(size_t)(tt + u) * DIM];
#pragma unroll
        for (int u = 0; u < 8; u++) {
            const float4 A  = wts[(tt + u) * 4 + 0];
            const float4 B  = wts[(tt + u) * 4 + 1];
            const float4 C  = wts[(tt + u) * 4 + 2];
            const float4 Dv = wts[(tt + u) * 4 + 3];
            acc[0]  = fmaf(A.x,  xv[u], acc[0]);  acc[1]  = fmaf(A.y,  xv[u], acc[1]);
            acc[2]  = fmaf(A.z,  xv[u], acc[2]);  acc[3]  = fmaf(A.w,  xv[u], acc[3]);
            acc[4]  = fmaf(B.x,  xv[u], acc[4]);  acc[5]  = fmaf(B.y,  xv[u], acc[5]);
            acc[6]  = fmaf(B.z,  xv[u], acc[6]);  acc[7]  = fmaf(B.w,  xv[u], acc[7]);
            acc[8]  = fmaf(C.x,  xv[u], acc[8]);  acc[9]  = fmaf(C.y,  xv[u], acc[9]);
            acc[10] = fmaf(C.z,  xv[u], acc[10]); acc[11] = fmaf(C.w,  xv[u], acc[11]);
            acc[12] = fmaf(Dv.x, xv[u], acc[12]); acc[13] = fmaf(Dv.y, xv[u], acc[13]);
            acc[14] = fmaf(Dv.z, xv[u], acc[14]); acc[15] = fmaf(Dv.w, xv[u], acc[15]);
        }
    }
    float* sp = g_spart + (size_t)blockIdx.y * (NE * DIM) + d;
#pragma unroll
    for (int e = 0; e < NE; e++) sp[e * DIM] = acc[e];
}

// ---------------- kernel 2b: reduce slot partials over YB ----------------
__global__ void __launch_bounds__(256) k_sred() {
    const int i = blockIdx.x * 256 + threadIdx.x;   // 0 .. NE*DIM-1
    float s = 0.f;
#pragma unroll
    for (int y = 0; y < YB; y++) s += g_spart[(size_t)y * (NE * DIM) + i];
    g_slots[i] = s;
}

// ---------------- kernel 3: h = slots @ w1^T (+b1). One warp per 4 rows ----
__global__ void __launch_bounds__(256) k_fc1(const float* __restrict__ w1,
                                             const float* __restrict__ b1) {
    const int q = blockIdx.x * 8 + (threadIdx.x >> 5);   // 0..8191
    const int lane = threadIdx.x & 31;
    const int r0 = q << 2;                               // 4 rows, same expert
    const int e = r0 >> 11;
    const float4* wr = reinterpret_cast<const float4*>(w1) + (size_t)r0 * 256 + lane;
    const float4* sr = reinterpret_cast<const float4*>(g_slots) + e * 256 + lane;
    float a0 = 0.f, a1 = 0.f, a2 = 0.f, a3 = 0.f;
#pragma unroll
    for (int k = 0; k < 8; k++) {
        const int o = k * 32;
        float4 s  = sr[o];
        float4 w0 = wr[o], w1v = wr[o + 256], w2v = wr[o + 512], w3v = wr[o + 768];
        a0 += w0.x*s.x + w0.y*s.y + w0.z*s.z + w0.w*s.w;
        a1 += w1v.x*s.x + w1v.y*s.y + w1v.z*s.z + w1v.w*s.w;
        a2 += w2v.x*s.x + w2v.y*s.y + w2v.z*s.z + w2v.w*s.w;
        a3 += w3v.x*s.x + w3v.y*s.y + w3v.z*s.z + w3v.w*s.w;
    }
#pragma unroll
    for (int m = 16; m > 0; m >>= 1) {
        a0 += __shfl_xor_sync(0xffffffffu, a0, m);
        a1 += __shfl_xor_sync(0xffffffffu, a1, m);
        a2 += __shfl_xor_sync(0xffffffffu, a2, m);
        a3 += __shfl_xor_sync(0xffffffffu, a3, m);
    }
    if (lane == 0) {
        float4 b = *reinterpret_cast<const float4*>(b1 + r0);
        *reinterpret_cast<float4*>(g_hbuf + r0) =
            make_float4(a0 + b.x, a1 + b.y, a2 + b.z, a3 + b.w);
    }
}

// ---------------- kernel 4: LayerNorm + exact GELU + scalars ----------------
__global__ void __launch_bounds__(256) k_ln_gelu(const float* __restrict__ ln_g,
                                                 const float* __restrict__ ln_b,
                                                 const float* __restrict__ rw,
                                                 float* __restrict__ out, int out_size) {
    __shared__ float red[256];
    const int tid = threadIdx.x;

    if (blockIdx.x == NE) {   // scalars: router_loss + entropy
        __shared__ float smean[NE];
        __shared__ float usage[NE];
        {   // usage from partials
            const int e = tid >> 4, sub = tid & 15;
            float s = 0.f;
#pragma unroll
            for (int i = 0; i < 16; i++) s += g_upart[e * RBLK + sub + i * 16];
#pragma unroll
            for (int m = 8; m > 0; m >>= 1) s += __shfl_xor_sync(0xffffffffu, s, m);
            if (sub == 0) usage[e] = s;
        }
        for (int e = 0; e < NE; e++) {
            float s = 0.f;
            for (int i = tid; i < DIM; i += 256) s += rw[e * DIM + i];
            red[tid] = s; __syncthreads();
            for (int st = 128; st; st >>= 1) {
                if (tid < st) red[tid] += red[tid + st];
                __syncthreads();
            }
            if (tid == 0) smean[e] = red[0] * (1.f / DIM);
            __syncthreads();
        }
        // entropy from partials
        red[tid] = (tid < RBLK) ? g_epart[tid] : 0.f;
        __syncthreads();
        for (int st = 128; st; st >>= 1) {
            if (tid < st) red[tid] += red[tid + st];
            __syncthreads();
        }
        if (tid == 0) {
            float m = -1e30f;
            for (int e2 = 0; e2 < NE; e2++) m = fmaxf(m, smean[e2]);
            float den = 0.f, pe[NE];
            for (int e2 = 0; e2 < NE; e2++) { pe[e2] = expf(smean[e2] - m); den += pe[e2]; }
            float loss = 0.f;
            for (int e2 = 0; e2 < NE; e2++)
                loss += (usage[e2] * (1.f / TKN)) * (pe[e2] / den);
            loss *= (float)NE;
            if (out_size > TKN * DIM)     out[TKN * DIM]     = loss;
            if (out_size > TKN * DIM + 1) out[TKN * DIM + 1] = red[0] * (1.f / TKN);
        }
        return;
    }

    const int e = blockIdx.x;
    float v[8]; float s = 0.f;
#pragma unroll
    for (int i = 0; i < 8; i++) { v[i] = g_hbuf[e * HID + tid + i * 256]; s += v[i]; }
    red[tid] = s; __syncthreads();
    for (int st = 128; st; st >>= 1) {
        if (tid < st) red[tid] += red[tid + st];
        __syncthreads();
    }
    const float mu = red[0] * (1.f / HID);
    __syncthreads();
    float s2 = 0.f;
#pragma unroll
    for (int i = 0; i < 8; i++) { float dv = v[i] - mu; s2 += dv * dv; }
    red[tid] = s2; __syncthreads();
    for (int st = 128; st; st >>= 1) {
        if (tid < st) red[tid] += red[tid + st];
        __syncthreads();
    }
    const float rstd = rsqrtf(red[0] * (1.f / HID) + 1e-5f);
#pragma unroll
    for (int i = 0; i < 8; i++) {
        int idx = e * HID + tid + i * 256;
        float hv = (v[i] - mu) * rstd * ln_g[idx] + ln_b[idx];
        g_hbuf[idx] = hv * 0.5f * (1.f + erff(hv * 0.70710678118654752f));
    }
}

// ---------------- kernel 5: slot_out = h @ w2^T (+b2). One warp per 4 rows --
__global__ void __launch_bounds__(256) k_fc2(const float* __restrict__ w2,
                                             const float* __restrict__ b2) {
    const int q = blockIdx.x * 8 + (threadIdx.x >> 5);   // 0..4095
    const int lane = threadIdx.x & 31;
    const int r0 = q << 2;
    const int e = r0 >> 10;
    const float4* wr = reinterpret_cast<const float4*>(w2) + (size_t)r0 * 512 + lane;
    const float4* hr = reinterpret_cast<const float4*>(g_hbuf) + e * 512 + lane;
    float a0 = 0.f, a1 = 0.f, a2 = 0.f, a3 = 0.f;
#pragma unroll
    for (int k = 0; k < 16; k++) {
        const int o = k * 32;
        float4 h  = hr[o];
        float4 w0 = wr[o], w1v = wr[o + 512], w2v = wr[o + 1024], w3v = wr[o + 1536];
        a0 += w0.x*h.x + w0.y*h.y + w0.z*h.z + w0.w*h.w;
        a1 += w1v.x*h.x + w1v.y*h.y + w1v.z*h.z + w1v.w*h.w;
        a2 += w2v.x*h.x + w2v.y*h.y + w2v.z*h.z + w2v.w*h.w;
        a3 += w3v.x*h.x + w3v.y*h.y + w3v.z*h.z + w3v.w*h.w;
    }
#pragma unroll
    for (int m = 16; m > 0; m >>= 1) {
        a0 += __shfl_xor_sync(0xffffffffu, a0, m);
        a1 += __shfl_xor_sync(0xffffffffu, a1, m);
        a2 += __shfl_xor_sync(0xffffffffu, a2, m);
        a3 += __shfl_xor_sync(0xffffffffu, a3, m);
    }
    if (lane == 0) {
        float4 b = *reinterpret_cast<const float4*>(b2 + r0);
        *reinterpret_cast<float4*>(g_sout + r0) =
            make_float4(a0 + b.x, a1 + b.y, a2 + b.z, a3 + b.w);
    }
}

// ---------------- kernel 6: out = combine @ slot_out ----------------
__global__ void __launch_bounds__(256) k_out(float* __restrict__ out) {
    __shared__ float comb[8 * NE];
    const int tid = threadIdx.x;
    const int tbase = blockIdx.x * 8;
    if (tid < 128) comb[tid] = g_comb[tbase * NE + tid];
    __syncthreads();

    const float4* so = reinterpret_cast<const float4*>(g_sout);
    float4 acc[8];
#pragma unroll
    for (int j = 0; j < 8; j++) acc[j] = make_float4(0.f, 0.f, 0.f, 0.f);
#pragma unroll
    for (int e = 0; e < NE; e++) {
        float4 s = so[e * 256 + tid];
#pragma unroll
        for (int j = 0; j < 8; j++) {
            float c = comb[j * NE + e];
            acc[j].x = fmaf(c, s.x, acc[j].x);
            acc[j].y = fmaf(c, s.y, acc[j].y);
            acc[j].z = fmaf(c, s.z, acc[j].z);
            acc[j].w = fmaf(c, s.w, acc[j].w);
        }
    }
    float4* o4 = reinterpret_cast<float4*>(out);
#pragma unroll
    for (int j = 0; j < 8; j++)
        o4[(size_t)(tbase + j) * 256 + tid] = acc[j];
}

// ---------------- launch ----------------
extern "C" void kernel_launch(void* const* d_in, const int* in_sizes, int n_in,
                              void* d_out, int out_size) {
    const float* x    = (const float*)d_in[0];
    const float* rw   = (const float*)d_in[1];
    const float* w1   = (const float*)d_in[2];
    const float* b1   = (const float*)d_in[3];
    const float* ln_g = (const float*)d_in[4];
    const float* ln_b = (const float*)d_in[5];
    const float* w2   = (const float*)d_in[6];
    const float* b2   = (const float*)d_in[7];
    float* out = (float*)d_out;

    cudaFuncSetAttribute((const void*)k_router,
                         cudaFuncAttributeMaxDynamicSharedMemorySize, 65536);

    k_router<<<RBLK, 256, 65536>>>(x, rw);
    k_slots<<<dim3(DIM / 256, YB), 256>>>(x);
    k_sred<<<(NE * DIM) / 256, 256>>>();
    k_fc1<<<(NE * HID) / 32, 256>>>(w1, b1);
    k_ln_gelu<<<NE + 1, 256>>>(ln_g, ln_b, rw, out, out_size);
    k_fc2<<<(NE * DIM) / 32, 256>>>(w2, b2);
    k_out<<<TKN / 8, 256>>>(out);
}

// round 16
// speedup vs baseline: 1.4267x; 1.4267x over previous
#include <cuda_runtime.h>
#include <math.h>

#define TKN 8192
#define DIM 1024
#define HID 2048
#define NE  16
#define RBLK 256            // router blocks (TKN/32)
#define YB  64              // slots token-blocks (TKN/128)

// ---------------- scratch (no allocation allowed) ----------------
__device__ float g_exps[TKN * NE];      // exp(logits) (dispatch numerator)
__device__ float g_comb[TKN * NE];      // combine = row softmax
__device__ float g_cpart[NE * RBLK];    // per-block colsum partials [e][block]
__device__ float g_upart[NE * RBLK];    // per-block usage partials  [e][block]
__device__ float g_epart[RBLK];         // per-block entropy partials
__device__ float g_spart[YB * NE * DIM];// per-y-block slot partials [y][e][d]
__device__ float g_slots[NE * DIM];     // dispatch^T @ x
__device__ float g_hbuf[NE * HID];      // fc1 out -> LN+GELU in place
__device__ float g_sout[NE * DIM];      // fc2 out

// ---------------- kernel 1: logits + both softmaxes + partial stats -------
// 256 blocks x 256 threads. Warp handles 4 tokens x 16 experts (x read ONCE).
// Reduction: distributed butterfly — 62 SHFLs/warp, results land 2-per-lane.
__global__ void __launch_bounds__(256) k_router(const float* __restrict__ x,
                                                const float* __restrict__ rw) {
    extern __shared__ float4 rwsh[];          // 16 * 256 float4 = 64 KB
    __shared__ float lsh[32 * NE];            // logit tile (32 tokens x 16 experts)
    const int tid = threadIdx.x;

    const float4* rw4 = reinterpret_cast<const float4*>(rw);
#pragma unroll
    for (int i = 0; i < 16; i++) rwsh[tid + i * 256] = rw4[tid + i * 256];
    __syncthreads();

    const int warp = tid >> 5, lane = tid & 31;
    const int t0 = blockIdx.x * 32 + warp * 4;

    // a[v], v = e*4 + j  (e: expert 0..15, j: token 0..3)
    float a[64];
#pragma unroll
    for (int v = 0; v < 64; v++) a[v] = 0.f;

    const float4* x4 = reinterpret_cast<const float4*>(x);
#pragma unroll
    for (int k = 0; k < 8; k++) {
        float4 xv[4];
#pragma unroll
        for (int j = 0; j < 4; j++)
            xv[j] = x4[(size_t)(t0 + j) * 256 + k * 32 + lane];
#pragma unroll
        for (int e = 0; e < 16; e++) {
            float4 r = rwsh[e * 256 + k * 32 + lane];
#pragma unroll
            for (int j = 0; j < 4; j++) {
                a[e * 4 + j] = fmaf(xv[j].x, r.x, a[e * 4 + j]);
                a[e * 4 + j] = fmaf(xv[j].y, r.y, a[e * 4 + j]);
                a[e * 4 + j] = fmaf(xv[j].z, r.z, a[e * 4 + j]);
                a[e * 4 + j] = fmaf(xv[j].w, r.w, a[e * 4 + j]);
            }
        }
    }
    // distributed butterfly reduce: after 5 steps lane l holds 2 fully-reduced
    // values: v = (l<<1)|q  ->  e = l>>1, j = ((l&1)<<1)|q
#pragma unroll
    for (int s = 0; s < 5; s++) {
        const int m    = 16 >> s;
        const int half = 32 >> s;
        const bool up  = (lane & m) != 0;
#pragma unroll
        for (int i = 0; i < half; i++) {
            float mine = up ? a[i] : a[i + half];
            float keep = up ? a[i + half] : a[i];
            float recv = __shfl_xor_sync(0xffffffffu, mine, m);
            a[i] = keep + recv;
        }
    }
    {
        const int e  = lane >> 1;
        const int j0 = (lane & 1) << 1;
        lsh[(warp * 4 + j0)     * NE + e] = a[0];
        lsh[(warp * 4 + j0 + 1) * NE + e] = a[1];
    }
    __syncthreads();

    // warp 0: row softmax over 16 experts, one token per lane (32 tokens)
    if (tid < 32) {
        const int t = blockIdx.x * 32 + tid;
        float l[16], raw[16], comb[16];
        float mx = -1e30f;
#pragma unroll
        for (int e = 0; e < NE; e++) { l[e] = lsh[tid * NE + e]; mx = fmaxf(mx, l[e]); }
        float den = 0.f;
#pragma unroll
        for (int e = 0; e < NE; e++) { comb[e] = expf(l[e] - mx); den += comb[e]; }
        const float rden = 1.0f / den;
        float ent = 0.f;
#pragma unroll
        for (int e = 0; e < NE; e++) {
            comb[e] *= rden;
            raw[e]   = expf(l[e]);
            ent     -= comb[e] * logf(comb[e] + 1e-8f);
        }
#pragma unroll
        for (int e = 0; e < NE; e++) {
            g_exps[t * NE + e] = raw[e];
            g_comb[t * NE + e] = comb[e];
        }
#pragma unroll
        for (int e = 0; e < NE; e++) {
            float cs = raw[e], us = comb[e];
#pragma unroll
            for (int m = 16; m > 0; m >>= 1) {
                cs += __shfl_xor_sync(0xffffffffu, cs, m);
                us += __shfl_xor_sync(0xffffffffu, us, m);
            }
            if (tid == e) {
                g_cpart[e * RBLK + blockIdx.x] = cs;
                g_upart[e * RBLK + blockIdx.x] = us;
            }
        }
#pragma unroll
        for (int m = 16; m > 0; m >>= 1)
            ent += __shfl_xor_sync(0xffffffffu, ent, m);
        if (tid == 0) g_epart[blockIdx.x] = ent;
    }
}

// ---------------- kernel 2: slot partials = dispatch^T @ x (per y-block) ---
__global__ void __launch_bounds__(256) k_slots(const float* __restrict__ x) {
    __shared__ float4 wts[128 * 4];
    __shared__ float  inv[NE];
    const int tid = threadIdx.x;
    {   // reduce colsum partials: 16 threads per expert (xor masks stay in-half-warp)
        const int e = tid >> 4, sub = tid & 15;
        float s = 0.f;
#pragma unroll
        for (int i = 0; i < 16; i++) s += g_cpart[e * RBLK + sub + i * 16];
#pragma unroll
        for (int m = 8; m > 0; m >>= 1) s += __shfl_xor_sync(0xffffffffu, s, m);
        if (sub == 0) inv[e] = 1.0f / s;
    }
    __syncthreads();

    const int tbase = blockIdx.y * 128;
    if (tid < 128) {
        const float4* ge = reinterpret_cast<const float4*>(g_exps) + (size_t)(tbase + tid) * 4;
        float4 a = ge[0], b = ge[1], c = ge[2], d4 = ge[3];
        a.x *= inv[0];  a.y *= inv[1];  a.z *= inv[2];  a.w *= inv[3];
        b.x *= inv[4];  b.y *= inv[5];  b.z *= inv[6];  b.w *= inv[7];
        c.x *= inv[8];  c.y *= inv[9];  c.z *= inv[10]; c.w *= inv[11];
        d4.x *= inv[12]; d4.y *= inv[13]; d4.z *= inv[14]; d4.w *= inv[15];
        wts[tid * 4 + 0] = a; wts[tid * 4 + 1] = b;
        wts[tid * 4 + 2] = c; wts[tid * 4 + 3] = d4;
    }
    __syncthreads();

    const int d = blockIdx.x * 256 + tid;
    const float* xp = x + (size_t)tbase * DIM + d;
    float acc[NE];
#pragma unroll
    for (int e = 0; e < NE; e++) acc[e] = 0.f;

    for (int tt = 0; tt < 128; tt += 8) {
        float xv[8];
#pragma unroll
        for (int u = 0; u < 8; u++) xv[u] = xp[(size_t)(tt + u) * DIM];
#pragma unroll
        for (int u = 0; u < 8; u++) {
            const float4 A  = wts[(tt + u) * 4 + 0];
            const float4 B  = wts[(tt + u) * 4 + 1];
            const float4 C  = wts[(tt + u) * 4 + 2];
            const float4 Dv = wts[(tt + u) * 4 + 3];
            acc[0]  = fmaf(A.x,  xv[u], acc[0]);  acc[1]  = fmaf(A.y,  xv[u], acc[1]);
            acc[2]  = fmaf(A.z,  xv[u], acc[2]);  acc[3]  = fmaf(A.w,  xv[u], acc[3]);
            acc[4]  = fmaf(B.x,  xv[u], acc[4]);  acc[5]  = fmaf(B.y,  xv[u], acc[5]);
            acc[6]  = fmaf(B.z,  xv[u], acc[6]);  acc[7]  = fmaf(B.w,  xv[u], acc[7]);
            acc[8]  = fmaf(C.x,  xv[u], acc[8]);  acc[9]  = fmaf(C.y,  xv[u], acc[9]);
            acc[10] = fmaf(C.z,  xv[u], acc[10]); acc[11] = fmaf(C.w,  xv[u], acc[11]);
            acc[12] = fmaf(Dv.x, xv[u], acc[12]); acc[13] = fmaf(Dv.y, xv[u], acc[13]);
            acc[14] = fmaf(Dv.z, xv[u], acc[14]); acc[15] = fmaf(Dv.w, xv[u], acc[15]);
        }
    }
    float* sp = g_spart + (size_t)blockIdx.y * (NE * DIM) + d;
#pragma unroll
    for (int e = 0; e < NE; e++) sp[e * DIM] = acc[e];
}

// ---------------- kernel 2b: reduce slot partials over YB ----------------
__global__ void __launch_bounds__(256) k_sred() {
    const int i = blockIdx.x * 256 + threadIdx.x;
    float s = 0.f;
#pragma unroll
    for (int y = 0; y < YB; y++) s += g_spart[(size_t)y * (NE * DIM) + i];
    g_slots[i] = s;
}

// ---------------- kernel 3: h = slots @ w1^T (+b1). One warp per 4 rows ----
__global__ void __launch_bounds__(256) k_fc1(const float* __restrict__ w1,
                                             const float* __restrict__ b1) {
    const int q = blockIdx.x * 8 + (threadIdx.x >> 5);
    const int lane = threadIdx.x & 31;
    const int r0 = q << 2;
    const int e = r0 >> 11;
    const float4* wr = reinterpret_cast<const float4*>(w1) + (size_t)r0 * 256 + lane;
    const float4* sr = reinterpret_cast<const float4*>(g_slots) + e * 256 + lane;
    float a0 = 0.f, a1 = 0.f, a2 = 0.f, a3 = 0.f;
#pragma unroll
    for (int k = 0; k < 8; k++) {
        const int o = k * 32;
        float4 s  = sr[o];
        float4 w0 = wr[o], w1v = wr[o + 256], w2v = wr[o + 512], w3v = wr[o + 768];
        a0 += w0.x*s.x + w0.y*s.y + w0.z*s.z + w0.w*s.w;
        a1 += w1v.x*s.x + w1v.y*s.y + w1v.z*s.z + w1v.w*s.w;
        a2 += w2v.x*s.x + w2v.y*s.y + w2v.z*s.z + w2v.w*s.w;
        a3 += w3v.x*s.x + w3v.y*s.y + w3v.z*s.z + w3v.w*s.w;
    }
#pragma unroll
    for (int m = 16; m > 0; m >>= 1) {
        a0 += __shfl_xor_sync(0xffffffffu, a0, m);
        a1 += __shfl_xor_sync(0xffffffffu, a1, m);
        a2 += __shfl_xor_sync(0xffffffffu, a2, m);
        a3 += __shfl_xor_sync(0xffffffffu, a3, m);
    }
    if (lane == 0) {
        float4 b = *reinterpret_cast<const float4*>(b1 + r0);
        *reinterpret_cast<float4*>(g_hbuf + r0) =
            make_float4(a0 + b.x, a1 + b.y, a2 + b.z, a3 + b.w);
    }
}

// ---------------- kernel 4: LayerNorm + exact GELU + scalars ----------------
__global__ void __launch_bounds__(256) k_ln_gelu(const float* __restrict__ ln_g,
                                                 const float* __restrict__ ln_b,
                                                 const float* __restrict__ rw,
                                                 float* __restrict__ out, int out_size) {
    __shared__ float red[256];
    const int tid = threadIdx.x;

    if (blockIdx.x == NE) {   // scalars: router_loss + entropy (warp-parallel)
        __shared__ float smean[NE];
        __shared__ float usage[NE];
        const int warp = tid >> 5, lane = tid & 31;
        {   // usage from partials
            const int e = tid >> 4, sub = tid & 15;
            float s = 0.f;
#pragma unroll
            for (int i = 0; i < 16; i++) s += g_upart[e * RBLK + sub + i * 16];
#pragma unroll
            for (int m = 8; m > 0; m >>= 1) s += __shfl_xor_sync(0xffffffffu, s, m);
            if (sub == 0) usage[e] = s;
        }
        // rw row means: warp w handles experts 2w, 2w+1 (lane reads 8 float4)
#pragma unroll
        for (int p = 0; p < 2; p++) {
            const int e = warp * 2 + p;
            const float4* r4 = reinterpret_cast<const float4*>(rw + e * DIM);
            float s = 0.f;
#pragma unroll
            for (int i = 0; i < 8; i++) {
                float4 v = r4[lane + i * 32];
                s += v.x + v.y + v.z + v.w;
            }
#pragma unroll
            for (int m = 16; m > 0; m >>= 1) s += __shfl_xor_sync(0xffffffffu, s, m);
            if (lane == 0) smean[e] = s * (1.f / DIM);
        }
        // entropy from partials
        red[tid] = g_epart[tid];
        __syncthreads();
        for (int st = 128; st; st >>= 1) {
            if (tid < st) red[tid] += red[tid + st];
            __syncthreads();
        }
        if (tid == 0) {
            float m = -1e30f;
            for (int e2 = 0; e2 < NE; e2++) m = fmaxf(m, smean[e2]);
            float den = 0.f, pe[NE];
            for (int e2 = 0; e2 < NE; e2++) { pe[e2] = expf(smean[e2] - m); den += pe[e2]; }
            float loss = 0.f;
            for (int e2 = 0; e2 < NE; e2++)
                loss += (usage[e2] * (1.f / TKN)) * (pe[e2] / den);
            loss *= (float)NE;
            if (out_size > TKN * DIM)     out[TKN * DIM]     = loss;
            if (out_size > TKN * DIM + 1) out[TKN * DIM + 1] = red[0] * (1.f / TKN);
        }
        return;
    }

    const int e = blockIdx.x;
    float v[8]; float s = 0.f;
#pragma unroll
    for (int i = 0; i < 8; i++) { v[i] = g_hbuf[e * HID + tid + i * 256]; s += v[i]; }
    red[tid] = s; __syncthreads();
    for (int st = 128; st; st >>= 1) {
        if (tid < st) red[tid] += red[tid + st];
        __syncthreads();
    }
    const float mu = red[0] * (1.f / HID);
    __syncthreads();
    float s2 = 0.f;
#pragma unroll
    for (int i = 0; i < 8; i++) { float dv = v[i] - mu; s2 += dv * dv; }
    red[tid] = s2; __syncthreads();
    for (int st = 128; st; st >>= 1) {
        if (tid < st) red[tid] += red[tid + st];
        __syncthreads();
    }
    const float rstd = rsqrtf(red[0] * (1.f / HID) + 1e-5f);
#pragma unroll
    for (int i = 0; i < 8; i++) {
        int idx = e * HID + tid + i * 256;
        float hv = (v[i] - mu) * rstd * ln_g[idx] + ln_b[idx];
        g_hbuf[idx] = hv * 0.5f * (1.f + erff(hv * 0.70710678118654752f));
    }
}

// ---------------- kernel 5: slot_out = h @ w2^T (+b2). One warp per 4 rows --
__global__ void __launch_bounds__(256) k_fc2(const float* __restrict__ w2,
                                             const float* __restrict__ b2) {
    const int q = blockIdx.x * 8 + (threadIdx.x >> 5);
    const int lane = threadIdx.x & 31;
    const int r0 = q << 2;
    const int e = r0 >> 10;
    const float4* wr = reinterpret_cast<const float4*>(w2) + (size_t)r0 * 512 + lane;
    const float4* hr = reinterpret_cast<const float4*>(g_hbuf) + e * 512 + lane;
    float a0 = 0.f, a1 = 0.f, a2 = 0.f, a3 = 0.f;
#pragma unroll
    for (int k = 0; k < 16; k++) {
        const int o = k * 32;
        float4 h  = hr[o];
        float4 w0 = wr[o], w1v = wr[o + 512], w2v = wr[o + 1024], w3v = wr[o + 1536];
        a0 += w0.x*h.x + w0.y*h.y + w0.z*h.z + w0.w*h.w;
        a1 += w1v.x*h.x + w1v.y*h.y + w1v.z*h.z + w1v.w*h.w;
        a2 += w2v.x*h.x + w2v.y*h.y + w2v.z*h.z + w2v.w*h.w;
        a3 += w3v.x*h.x + w3v.y*h.y + w3v.z*h.z + w3v.w*h.w;
    }
#pragma unroll
    for (int m = 16; m > 0; m >>= 1) {
        a0 += __shfl_xor_sync(0xffffffffu, a0, m);
        a1 += __shfl_xor_sync(0xffffffffu, a1, m);
        a2 += __shfl_xor_sync(0xffffffffu, a2, m);
        a3 += __shfl_xor_sync(0xffffffffu, a3, m);
    }
    if (lane == 0) {
        float4 b = *reinterpret_cast<const float4*>(b2 + r0);
        *reinterpret_cast<float4*>(g_sout + r0) =
            make_float4(a0 + b.x, a1 + b.y, a2 + b.z, a3 + b.w);
    }
}

// ---------------- kernel 6: out = combine @ slot_out (16 tokens/block) -----
__global__ void __launch_bounds__(256) k_out(float* __restrict__ out) {
    __shared__ float comb[16 * NE];
    const int tid = threadIdx.x;
    const int tbase = blockIdx.x * 16;
    comb[tid] = g_comb[tbase * NE + tid];
    __syncthreads();

    const float4* so = reinterpret_cast<const float4*>(g_sout);
    float4 acc[16];
#pragma unroll
    for (int j = 0; j < 16; j++) acc[j] = make_float4(0.f, 0.f, 0.f, 0.f);
#pragma unroll
    for (int e = 0; e < NE; e++) {
        float4 s = so[e * 256 + tid];
#pragma unroll
        for (int j = 0; j < 16; j++) {
            float c = comb[j * NE + e];
            acc[j].x = fmaf(c, s.x, acc[j].x);
            acc[j].y = fmaf(c, s.y, acc[j].y);
            acc[j].z = fmaf(c, s.z, acc[j].z);
            acc[j].w = fmaf(c, s.w, acc[j].w);
        }
    }
    float4* o4 = reinterpret_cast<float4*>(out);
#pragma unroll
    for (int j = 0; j < 16; j++)
        o4[(size_t)(tbase + j) * 256 + tid] = acc[j];
}

// ---------------- launch ----------------
extern "C" void kernel_launch(void* const* d_in, const int* in_sizes, int n_in,
                              void* d_out, int out_size) {
    const float* x    = (const float*)d_in[0];
    const float* rw   = (const float*)d_in[1];
    const float* w1   = (const float*)d_in[2];
    const float* b1   = (const float*)d_in[3];
    const float* ln_g = (const float*)d_in[4];
    const float* ln_b = (const float*)d_in[5];
    const float* w2   = (const float*)d_in[6];
    const float* b2   = (const float*)d_in[7];
    float* out = (float*)d_out;

    cudaFuncSetAttribute((const void*)k_router,
                         cudaFuncAttributeMaxDynamicSharedMemorySize, 65536);

    k_router<<<RBLK, 256, 65536>>>(x, rw);
    k_slots<<<dim3(DIM / 256, YB), 256>>>(x);
    k_sred<<<(NE * DIM) / 256, 256>>>();
    k_fc1<<<(NE * HID) / 32, 256>>>(w1, b1);
    k_ln_gelu<<<NE + 1, 256>>>(ln_g, ln_b, rw, out, out_size);
    k_fc2<<<(NE * DIM) / 32, 256>>>(w2, b2);
    k_out<<<TKN / 16, 256>>>(out);
}

// round 17
// speedup vs baseline: 1.6104x; 1.1288x over previous
#include <cuda_runtime.h>
#include <math.h>

#define TKN 8192
#define DIM 1024
#define HID 2048
#define NE  16
#define RBLK 256            // router blocks (TKN/32)
#define YB  64              // slots token-blocks (TKN/128)

// ---------------- scratch (no allocation allowed) ----------------
__device__ float g_exps[TKN * NE];      // exp(logits) (dispatch numerator)
__device__ float g_comb[TKN * NE];      // combine = row softmax
__device__ float g_cpart[NE * RBLK];    // per-block colsum partials [e][block]
__device__ float g_upart[NE * RBLK];    // per-block usage partials  [e][block]
__device__ float g_epart[RBLK];         // per-block entropy partials
__device__ float g_spart[YB * NE * DIM];// per-y-block slot partials [y][e][d]
__device__ float g_slots[NE * DIM];     // dispatch^T @ x
__device__ float g_hbuf[NE * HID];      // fc1 out (raw, pre-LN)
__device__ float g_sout[NE * DIM];      // fc2 out

// ---------------- kernel 1: logits + both softmaxes + partial stats -------
// 256 blocks x 256 threads. Warp handles 4 tokens x 16 experts (x read ONCE).
// Reduction: distributed butterfly — 62 SHFLs/warp, results land 2-per-lane.
__global__ void __launch_bounds__(256) k_router(const float* __restrict__ x,
                                                const float* __restrict__ rw) {
    extern __shared__ float4 rwsh[];          // 16 * 256 float4 = 64 KB
    __shared__ float lsh[32 * NE];            // logit tile (32 tokens x 16 experts)
    const int tid = threadIdx.x;

    const float4* rw4 = reinterpret_cast<const float4*>(rw);
#pragma unroll
    for (int i = 0; i < 16; i++) rwsh[tid + i * 256] = rw4[tid + i * 256];
    __syncthreads();

    const int warp = tid >> 5, lane = tid & 31;
    const int t0 = blockIdx.x * 32 + warp * 4;

    float a[64];                              // a[e*4+j]
#pragma unroll
    for (int v = 0; v < 64; v++) a[v] = 0.f;

    const float4* x4 = reinterpret_cast<const float4*>(x);
#pragma unroll
    for (int k = 0; k < 8; k++) {
        float4 xv[4];
#pragma unroll
        for (int j = 0; j < 4; j++)
            xv[j] = x4[(size_t)(t0 + j) * 256 + k * 32 + lane];
#pragma unroll
        for (int e = 0; e < 16; e++) {
            float4 r = rwsh[e * 256 + k * 32 + lane];
#pragma unroll
            for (int j = 0; j < 4; j++) {
                a[e * 4 + j] = fmaf(xv[j].x, r.x, a[e * 4 + j]);
                a[e * 4 + j] = fmaf(xv[j].y, r.y, a[e * 4 + j]);
                a[e * 4 + j] = fmaf(xv[j].z, r.z, a[e * 4 + j]);
                a[e * 4 + j] = fmaf(xv[j].w, r.w, a[e * 4 + j]);
            }
        }
    }
    // distributed butterfly: lane l ends with v=(l<<1)|q -> e=l>>1, j=((l&1)<<1)|q
#pragma unroll
    for (int s = 0; s < 5; s++) {
        const int m    = 16 >> s;
        const int half = 32 >> s;
        const bool up  = (lane & m) != 0;
#pragma unroll
        for (int i = 0; i < half; i++) {
            float mine = up ? a[i] : a[i + half];
            float keep = up ? a[i + half] : a[i];
            float recv = __shfl_xor_sync(0xffffffffu, mine, m);
            a[i] = keep + recv;
        }
    }
    {
        const int e  = lane >> 1;
        const int j0 = (lane & 1) << 1;
        lsh[(warp * 4 + j0)     * NE + e] = a[0];
        lsh[(warp * 4 + j0 + 1) * NE + e] = a[1];
    }
    __syncthreads();

    if (tid < 32) {                           // row softmax, one token per lane
        const int t = blockIdx.x * 32 + tid;
        float l[16], raw[16], comb[16];
        float mx = -1e30f;
#pragma unroll
        for (int e = 0; e < NE; e++) { l[e] = lsh[tid * NE + e]; mx = fmaxf(mx, l[e]); }
        float den = 0.f;
#pragma unroll
        for (int e = 0; e < NE; e++) { comb[e] = expf(l[e] - mx); den += comb[e]; }
        const float rden = 1.0f / den;
        float ent = 0.f;
#pragma unroll
        for (int e = 0; e < NE; e++) {
            comb[e] *= rden;
            raw[e]   = expf(l[e]);
            ent     -= comb[e] * logf(comb[e] + 1e-8f);
        }
#pragma unroll
        for (int e = 0; e < NE; e++) {
            g_exps[t * NE + e] = raw[e];
            g_comb[t * NE + e] = comb[e];
        }
#pragma unroll
        for (int e = 0; e < NE; e++) {
            float cs = raw[e], us = comb[e];
#pragma unroll
            for (int m = 16; m > 0; m >>= 1) {
                cs += __shfl_xor_sync(0xffffffffu, cs, m);
                us += __shfl_xor_sync(0xffffffffu, us, m);
            }
            if (tid == e) {
                g_cpart[e * RBLK + blockIdx.x] = cs;
                g_upart[e * RBLK + blockIdx.x] = us;
            }
        }
#pragma unroll
        for (int m = 16; m > 0; m >>= 1)
            ent += __shfl_xor_sync(0xffffffffu, ent, m);
        if (tid == 0) g_epart[blockIdx.x] = ent;
    }
}

// ---------------- kernel 2: slot partials = dispatch^T @ x (per y-block) ---
__global__ void __launch_bounds__(256) k_slots(const float* __restrict__ x) {
    __shared__ float4 wts[128 * 4];
    __shared__ float  inv[NE];
    const int tid = threadIdx.x;
    {   // reduce colsum partials: 16 threads per expert
        const int e = tid >> 4, sub = tid & 15;
        float s = 0.f;
#pragma unroll
        for (int i = 0; i < 16; i++) s += g_cpart[e * RBLK + sub + i * 16];
#pragma unroll
        for (int m = 8; m > 0; m >>= 1) s += __shfl_xor_sync(0xffffffffu, s, m);
        if (sub == 0) inv[e] = 1.0f / s;
    }
    __syncthreads();

    const int tbase = blockIdx.y * 128;
    if (tid < 128) {
        const float4* ge = reinterpret_cast<const float4*>(g_exps) + (size_t)(tbase + tid) * 4;
        float4 a = ge[0], b = ge[1], c = ge[2], d4 = ge[3];
        a.x *= inv[0];  a.y *= inv[1];  a.z *= inv[2];  a.w *= inv[3];
        b.x *= inv[4];  b.y *= inv[5];  b.z *= inv[6];  b.w *= inv[7];
        c.x *= inv[8];  c.y *= inv[9];  c.z *= inv[10]; c.w *= inv[11];
        d4.x *= inv[12]; d4.y *= inv[13]; d4.z *= inv[14]; d4.w *= inv[15];
        wts[tid * 4 + 0] = a; wts[tid * 4 + 1] = b;
        wts[tid * 4 + 2] = c; wts[tid * 4 + 3] = d4;
    }
    __syncthreads();

    const int d = blockIdx.x * 256 + tid;
    const float* xp = x + (size_t)tbase * DIM + d;
    float acc[NE];
#pragma unroll
    for (int e = 0; e < NE; e++) acc[e] = 0.f;

    for (int tt = 0; tt < 128; tt += 8) {
        float xv[8];
#pragma unroll
        for (int u = 0; u < 8; u++) xv[u] = xp[(size_t)(tt + u) * DIM];
#pragma unroll
        for (int u = 0; u < 8; u++) {
            const float4 A  = wts[(tt + u) * 4 + 0];
            const float4 B  = wts[(tt + u) * 4 + 1];
            const float4 C  = wts[(tt + u) * 4 + 2];
            const float4 Dv = wts[(tt + u) * 4 + 3];
            acc[0]  = fmaf(A.x,  xv[u], acc[0]);  acc[1]  = fmaf(A.y,  xv[u], acc[1]);
            acc[2]  = fmaf(A.z,  xv[u], acc[2]);  acc[3]  = fmaf(A.w,  xv[u], acc[3]);
            acc[4]  = fmaf(B.x,  xv[u], acc[4]);  acc[5]  = fmaf(B.y,  xv[u], acc[5]);
            acc[6]  = fmaf(B.z,  xv[u], acc[6]);  acc[7]  = fmaf(B.w,  xv[u], acc[7]);
            acc[8]  = fmaf(C.x,  xv[u], acc[8]);  acc[9]  = fmaf(C.y,  xv[u], acc[9]);
            acc[10] = fmaf(C.z,  xv[u], acc[10]); acc[11] = fmaf(C.w,  xv[u], acc[11]);
            acc[12] = fmaf(Dv.x, xv[u], acc[12]); acc[13] = fmaf(Dv.y, xv[u], acc[13]);
            acc[14] = fmaf(Dv.z, xv[u], acc[14]); acc[15] = fmaf(Dv.w, xv[u], acc[15]);
        }
    }
    float* sp = g_spart + (size_t)blockIdx.y * (NE * DIM) + d;
#pragma unroll
    for (int e = 0; e < NE; e++) sp[e * DIM] = acc[e];
}

// ---------------- kernel 2b: reduce slot partials; spare block = scalars ---
__global__ void __launch_bounds__(256) k_sred(const float* __restrict__ rw,
                                              float* __restrict__ out, int out_size) {
    const int tid = threadIdx.x;
    if (blockIdx.x == (NE * DIM) / 256) {     // scalar block: loss + entropy
        __shared__ float smean[NE];
        __shared__ float usage[NE];
        __shared__ float red[256];
        const int warp = tid >> 5, lane = tid & 31;
        {   // usage from partials
            const int e = tid >> 4, sub = tid & 15;
            float s = 0.f;
#pragma unroll
            for (int i = 0; i < 16; i++) s += g_upart[e * RBLK + sub + i * 16];
#pragma unroll
            for (int m = 8; m > 0; m >>= 1) s += __shfl_xor_sync(0xffffffffu, s, m);
            if (sub == 0) usage[e] = s;
        }
#pragma unroll
        for (int p = 0; p < 2; p++) {         // rw row means
            const int e = warp * 2 + p;
            const float4* r4 = reinterpret_cast<const float4*>(rw + e * DIM);
            float s = 0.f;
#pragma unroll
            for (int i = 0; i < 8; i++) {
                float4 v = r4[lane + i * 32];
                s += v.x + v.y + v.z + v.w;
            }
#pragma unroll
            for (int m = 16; m > 0; m >>= 1) s += __shfl_xor_sync(0xffffffffu, s, m);
            if (lane == 0) smean[e] = s * (1.f / DIM);
        }
        red[tid] = g_epart[tid];
        __syncthreads();
        for (int st = 128; st; st >>= 1) {
            if (tid < st) red[tid] += red[tid + st];
            __syncthreads();
        }
        if (tid == 0) {
            float m = -1e30f;
            for (int e2 = 0; e2 < NE; e2++) m = fmaxf(m, smean[e2]);
            float den = 0.f, pe[NE];
            for (int e2 = 0; e2 < NE; e2++) { pe[e2] = expf(smean[e2] - m); den += pe[e2]; }
            float loss = 0.f;
            for (int e2 = 0; e2 < NE; e2++)
                loss += (usage[e2] * (1.f / TKN)) * (pe[e2] / den);
            loss *= (float)NE;
            if (out_size > TKN * DIM)     out[TKN * DIM]     = loss;
            if (out_size > TKN * DIM + 1) out[TKN * DIM + 1] = red[0] * (1.f / TKN);
        }
        return;
    }
    const int i = blockIdx.x * 256 + tid;
    float s = 0.f;
#pragma unroll
    for (int y = 0; y < YB; y++) s += g_spart[(size_t)y * (NE * DIM) + i];
    g_slots[i] = s;
}

// ---------------- kernel 3: h = slots @ w1^T (+b1). Warp: 4 rows; slots in smem
__global__ void __launch_bounds__(256) k_fc1(const float* __restrict__ w1,
                                             const float* __restrict__ b1) {
    __shared__ float4 ssm[256];               // expert slot vector (4 KB)
    const int tid = threadIdx.x;
    const int warp = tid >> 5, lane = tid & 31;
    const int q = blockIdx.x * 8 + warp;
    const int r0 = q << 2;
    const int e = r0 >> 11;
    ssm[tid] = reinterpret_cast<const float4*>(g_slots)[e * 256 + tid];
    __syncthreads();

    const float4* wr = reinterpret_cast<const float4*>(w1) + (size_t)r0 * 256 + lane;
    float a0 = 0.f, a1 = 0.f, a2 = 0.f, a3 = 0.f;
#pragma unroll
    for (int k = 0; k < 8; k++) {
        const int o = k * 32;
        float4 s  = ssm[o + lane];
        float4 w0 = __ldcs(wr + o);
        float4 w1v = __ldcs(wr + o + 256);
        float4 w2v = __ldcs(wr + o + 512);
        float4 w3v = __ldcs(wr + o + 768);
        a0 += w0.x*s.x + w0.y*s.y + w0.z*s.z + w0.w*s.w;
        a1 += w1v.x*s.x + w1v.y*s.y + w1v.z*s.z + w1v.w*s.w;
        a2 += w2v.x*s.x + w2v.y*s.y + w2v.z*s.z + w2v.w*s.w;
        a3 += w3v.x*s.x + w3v.y*s.y + w3v.z*s.z + w3v.w*s.w;
    }
#pragma unroll
    for (int m = 16; m > 0; m >>= 1) {
        a0 += __shfl_xor_sync(0xffffffffu, a0, m);
        a1 += __shfl_xor_sync(0xffffffffu, a1, m);
        a2 += __shfl_xor_sync(0xffffffffu, a2, m);
        a3 += __shfl_xor_sync(0xffffffffu, a3, m);
    }
    if (lane == 0) {
        float4 b = *reinterpret_cast<const float4*>(b1 + r0);
        *reinterpret_cast<float4*>(g_hbuf + r0) =
            make_float4(a0 + b.x, a1 + b.y, a2 + b.z, a3 + b.w);
    }
}

// ---------------- kernel 4: fused LN+GELU prologue + slot_out = h @ w2^T ----
__global__ void __launch_bounds__(256) k_fc2(const float* __restrict__ w2,
                                             const float* __restrict__ b2,
                                             const float* __restrict__ ln_g,
                                             const float* __restrict__ ln_b) {
    __shared__ float4 hsm[512];               // LN+GELU'd h (8 KB)
    __shared__ float red[16];
    const int tid = threadIdx.x;
    const int warp = tid >> 5, lane = tid & 31;
    const int q = blockIdx.x * 8 + warp;
    const int r0 = q << 2;
    const int e = r0 >> 10;

    // ---- LN + GELU prologue (one-pass mean/var over 2048 values) ----
    const float4* h4 = reinterpret_cast<const float4*>(g_hbuf) + e * 512;
    float4 h0 = h4[tid], h1 = h4[256 + tid];
    float su = h0.x + h0.y + h0.z + h0.w + h1.x + h1.y + h1.z + h1.w;
    float sq = h0.x*h0.x + h0.y*h0.y + h0.z*h0.z + h0.w*h0.w
             + h1.x*h1.x + h1.y*h1.y + h1.z*h1.z + h1.w*h1.w;
#pragma unroll
    for (int m = 16; m > 0; m >>= 1) {
        su += __shfl_xor_sync(0xffffffffu, su, m);
        sq += __shfl_xor_sync(0xffffffffu, sq, m);
    }
    if (lane == 0) { red[warp] = su; red[8 + warp] = sq; }
    __syncthreads();
    float tsu = 0.f, tsq = 0.f;
#pragma unroll
    for (int i = 0; i < 8; i++) { tsu += red[i]; tsq += red[8 + i]; }
    const float mu   = tsu * (1.f / HID);
    const float rstd = rsqrtf(tsq * (1.f / HID) - mu * mu + 1e-5f);

    const float4* g4 = reinterpret_cast<const float4*>(ln_g) + e * 512;
    const float4* bb4 = reinterpret_cast<const float4*>(ln_b) + e * 512;
    {
        float4 g = g4[tid], bv = bb4[tid];
        float4 r;
        r.x = (h0.x - mu) * rstd * g.x + bv.x;
        r.y = (h0.y - mu) * rstd * g.y + bv.y;
        r.z = (h0.z - mu) * rstd * g.z + bv.z;
        r.w = (h0.w - mu) * rstd * g.w + bv.w;
        r.x = r.x * 0.5f * (1.f + erff(r.x * 0.70710678118654752f));
        r.y = r.y * 0.5f * (1.f + erff(r.y * 0.70710678118654752f));
        r.z = r.z * 0.5f * (1.f + erff(r.z * 0.70710678118654752f));
        r.w = r.w * 0.5f * (1.f + erff(r.w * 0.70710678118654752f));
        hsm[tid] = r;
        g = g4[256 + tid]; bv = bb4[256 + tid];
        r.x = (h1.x - mu) * rstd * g.x + bv.x;
        r.y = (h1.y - mu) * rstd * g.y + bv.y;
        r.z = (h1.z - mu) * rstd * g.z + bv.z;
        r.w = (h1.w - mu) * rstd * g.w + bv.w;
        r.x = r.x * 0.5f * (1.f + erff(r.x * 0.70710678118654752f));
        r.y = r.y * 0.5f * (1.f + erff(r.y * 0.70710678118654752f));
        r.z = r.z * 0.5f * (1.f + erff(r.z * 0.70710678118654752f));
        r.w = r.w * 0.5f * (1.f + erff(r.w * 0.70710678118654752f));
        hsm[256 + tid] = r;
    }
    __syncthreads();

    // ---- GEMV: 4 rows per warp, h from shared, streaming weights ----
    const float4* wr = reinterpret_cast<const float4*>(w2) + (size_t)r0 * 512 + lane;
    float a0 = 0.f, a1 = 0.f, a2 = 0.f, a3 = 0.f;
#pragma unroll
    for (int k = 0; k < 16; k++) {
        const int o = k * 32;
        float4 h  = hsm[o + lane];
        float4 w0 = __ldcs(wr + o);
        float4 w1v = __ldcs(wr + o + 512);
        float4 w2v = __ldcs(wr + o + 1024);
        float4 w3v = __ldcs(wr + o + 1536);
        a0 += w0.x*h.x + w0.y*h.y + w0.z*h.z + w0.w*h.w;
        a1 += w1v.x*h.x + w1v.y*h.y + w1v.z*h.z + w1v.w*h.w;
        a2 += w2v.x*h.x + w2v.y*h.y + w2v.z*h.z + w2v.w*h.w;
        a3 += w3v.x*h.x + w3v.y*h.y + w3v.z*h.z + w3v.w*h.w;
    }
#pragma unroll
    for (int m = 16; m > 0; m >>= 1) {
        a0 += __shfl_xor_sync(0xffffffffu, a0, m);
        a1 += __shfl_xor_sync(0xffffffffu, a1, m);
        a2 += __shfl_xor_sync(0xffffffffu, a2, m);
        a3 += __shfl_xor_sync(0xffffffffu, a3, m);
    }
    if (lane == 0) {
        float4 b = *reinterpret_cast<const float4*>(b2 + r0);
        *reinterpret_cast<float4*>(g_sout + r0) =
            make_float4(a0 + b.x, a1 + b.y, a2 + b.z, a3 + b.w);
    }
}

// ---------------- kernel 5: out = combine @ slot_out (16 tokens/block) -----
__global__ void __launch_bounds__(256) k_out(float* __restrict__ out) {
    __shared__ float comb[16 * NE];
    const int tid = threadIdx.x;
    const int tbase = blockIdx.x * 16;
    comb[tid] = g_comb[tbase * NE + tid];
    __syncthreads();

    const float4* so = reinterpret_cast<const float4*>(g_sout);
    float4 acc[16];
#pragma unroll
    for (int j = 0; j < 16; j++) acc[j] = make_float4(0.f, 0.f, 0.f, 0.f);
#pragma unroll
    for (int e = 0; e < NE; e++) {
        float4 s = so[e * 256 + tid];
#pragma unroll
        for (int j = 0; j < 16; j++) {
            float c = comb[j * NE + e];
            acc[j].x = fmaf(c, s.x, acc[j].x);
            acc[j].y = fmaf(c, s.y, acc[j].y);
            acc[j].z = fmaf(c, s.z, acc[j].z);
            acc[j].w = fmaf(c, s.w, acc[j].w);
        }
    }
    float4* o4 = reinterpret_cast<float4*>(out);
#pragma unroll
    for (int j = 0; j < 16; j++)
        o4[(size_t)(tbase + j) * 256 + tid] = acc[j];
}

// ---------------- launch ----------------
extern "C" void kernel_launch(void* const* d_in, const int* in_sizes, int n_in,
                              void* d_out, int out_size) {
    const float* x    = (const float*)d_in[0];
    const float* rw   = (const float*)d_in[1];
    const float* w1   = (const float*)d_in[2];
    const float* b1   = (const float*)d_in[3];
    const float* ln_g = (const float*)d_in[4];
    const float* ln_b = (const float*)d_in[5];
    const float* w2   = (const float*)d_in[6];
    const float* b2   = (const float*)d_in[7];
    float* out = (float*)d_out;

    cudaFuncSetAttribute((const void*)k_router,
                         cudaFuncAttributeMaxDynamicSharedMemorySize, 65536);

    k_router<<<RBLK, 256, 65536>>>(x, rw);
    k_slots<<<dim3(DIM / 256, YB), 256>>>(x);
    k_sred<<<(NE * DIM) / 256 + 1, 256>>>(rw, out, out_size);
    k_fc1<<<(NE * HID) / 32, 256>>>(w1, b1);
    k_fc2<<<(NE * DIM) / 32, 256>>>(w2, b2, ln_g, ln_b);
    k_out<<<TKN / 16, 256>>>(out);
}